// round 8
// baseline (speedup 1.0000x reference)
#include <cuda_runtime.h>
#include <cuda_bf16.h>
#include <math.h>
#include <stdint.h>

// Problem constants
#define BATCH   2
#define HW      64
#define SEQ     256
#define DMODEL  512
#define HEADS   8
#define DK      64
#define KSIZE   7
#define NEIGH   3

#define MROWS   (BATCH * HW * SEQ)      // 32768
#define QKV_N   (3 * HEADS * DK)        // 1536

// GEMM tiling: CTA 128x128, 4 warps, warp tile 64x64
#define BM 128
#define BN 128
#define BK 32
#define XS 40   // smem row stride (floats); XS mod 32 == 8 -> conflict-free LDS.64
#define GEMM_THREADS 128

// Scratch (allocation-free: __device__ globals)
__device__ float g_xt  [(size_t)MROWS * DMODEL];   //  64 MB (tf32, K-permuted)
__device__ float g_qkv [(size_t)MROWS * QKV_N];    // 201 MB
__device__ float g_att [(size_t)MROWS * DMODEL];   //  67 MB (tf32, K-permuted)
__device__ float g_wqkvT[(size_t)QKV_N * DMODEL];  //   3 MB (Wqkv^T, K-permuted)
__device__ float g_woutT[(size_t)DMODEL * DMODEL]; //   1 MB (Wout^T, K-permuted)

// ---------------------------------------------------------------------------
// Helpers
// ---------------------------------------------------------------------------
__device__ __forceinline__ float to_tf32(float x) {
    float y;
    asm("cvt.rna.tf32.f32 %0, %1;" : "=f"(y) : "f"(x));
    return y;
}

// In-8-chunk K permutation: k -> (k&~7) | ((k&3)<<1) | (k>>2&1).
// Applied to BOTH operands of each GEMM along K -> dot products invariant.
// Makes mma fragment k-pairs {t, t+4} adjacent in memory -> LDS.64.
__device__ __forceinline__ int permk(int k) {
    return (k & ~7) | ((k & 3) << 1) | ((k >> 2) & 1);
}

__device__ __forceinline__ uint32_t smem_u32(const void* p) {
    uint32_t a;
    asm("{ .reg .u64 t; cvta.to.shared.u64 t, %1; cvt.u32.u64 %0, t; }"
        : "=r"(a) : "l"(p));
    return a;
}

#define CP_ASYNC16(dst, src) \
    asm volatile("cp.async.cg.shared.global [%0], [%1], 16;" \
                 :: "r"(dst), "l"(src) : "memory")
#define CP_COMMIT() asm volatile("cp.async.commit_group;" ::: "memory")
#define CP_WAIT(n)  asm volatile("cp.async.wait_group %0;" :: "n"(n) : "memory")

__device__ __forceinline__ void mma_tf32(float* c, const uint32_t* a,
                                         const uint32_t* b) {
    asm volatile(
        "mma.sync.aligned.m16n8k8.row.col.f32.tf32.tf32.f32 "
        "{%0,%1,%2,%3}, {%4,%5,%6,%7}, {%8,%9}, {%0,%1,%2,%3};"
        : "+f"(c[0]), "+f"(c[1]), "+f"(c[2]), "+f"(c[3])
        : "r"(a[0]), "r"(a[1]), "r"(a[2]), "r"(a[3]),
          "r"(b[0]), "r"(b[1]));
}

// ---------------------------------------------------------------------------
// tf32 warp-MMA GEMM: C[M,N] = A[M,K] @ Bt[N,K]^T  (K-permuted operands)
// CTA 128x128, 128 threads, 4 warps @ 64x64 warp tile (2x2 warp grid).
// Double-buffered cp.async + DOUBLE-BUFFERED FRAGMENTS across kk-slices:
// frag(kk+1) is loaded before mma(kk) issues, so every LDS batch is covered
// by the 32 in-flight HMMAs of the previous slice.
// ---------------------------------------------------------------------------
template<int K>
__global__ __launch_bounds__(GEMM_THREADS, 2) void gemm_mma_tf32(
    const float* __restrict__ A, const float* __restrict__ Bt,
    float* __restrict__ C, int M, int N)
{
    extern __shared__ float sm[];
    float* Asf = sm;                       // [2][BM][XS]
    float* Bsf = sm + 2 * BM * XS;         // [2][BN][XS]
    const uint32_t as_u = smem_u32(Asf);
    const uint32_t bs_u = smem_u32(Bsf);

    const int tid  = threadIdx.x;
    const int wid  = tid >> 5;
    const int lane = tid & 31;
    const int gid  = lane >> 2;    // 0..7
    const int tig  = lane & 3;     // 0..3

    const int wm0 = (wid >> 1) * 64;   // warp m-offset (0 or 64)
    const int wn0 = (wid & 1) * 64;    // warp n-offset (0 or 64)

    const int mbase = blockIdx.y * BM;
    const int nbase = blockIdx.x * BN;
    const float* Ab = A  + (size_t)mbase * K;
    const float* Bb = Bt + (size_t)nbase * K;

    const int lrow = tid >> 3;          // 0..15
    const int lk4  = (tid & 7) << 2;    // 0,4,...,28

    auto load_stage = [&](int s, int buf) {
        const float* Asrc = Ab + (size_t)s * BK;
        const float* Bsrc = Bb + (size_t)s * BK;
        #pragma unroll
        for (int j = 0; j < 8; j++) {
            int row = lrow + 16 * j;
            uint32_t d = as_u + (((uint32_t)(buf * BM + row) * XS + lk4) << 2);
            CP_ASYNC16(d, Asrc + (size_t)row * K + lk4);
        }
        #pragma unroll
        for (int j = 0; j < 8; j++) {
            int row = lrow + 16 * j;
            uint32_t d = bs_u + (((uint32_t)(buf * BN + row) * XS + lk4) << 2);
            CP_ASYNC16(d, Bsrc + (size_t)row * K + lk4);
        }
    };

    float acc[4][8][4];
    #pragma unroll
    for (int mi = 0; mi < 4; mi++)
        #pragma unroll
        for (int ni = 0; ni < 8; ni++)
            #pragma unroll
            for (int q = 0; q < 4; q++) acc[mi][ni][q] = 0.0f;

    // Fragment double buffers
    uint32_t afr[2][4][4], bfr[2][8][2];

    // Fragment loader for kk-slice from smem buffer base pointers
    auto load_frag = [&](const float* Ab_s, const float* Bb_s, int kk, int pb) {
        const int k8 = kk * 8;
        #pragma unroll
        for (int mi = 0; mi < 4; mi++) {
            const float* r0 = Ab_s + (wm0 + mi * 16 + gid) * XS + k8 + 2 * tig;
            float2 f0 = *(const float2*)r0;
            float2 f8 = *(const float2*)(r0 + 8 * XS);
            afr[pb][mi][0] = __float_as_uint(f0.x);
            afr[pb][mi][1] = __float_as_uint(f8.x);
            afr[pb][mi][2] = __float_as_uint(f0.y);
            afr[pb][mi][3] = __float_as_uint(f8.y);
        }
        #pragma unroll
        for (int ni = 0; ni < 8; ni++) {
            const float* rn = Bb_s + (wn0 + ni * 8 + gid) * XS + k8 + 2 * tig;
            float2 fn = *(const float2*)rn;
            bfr[pb][ni][0] = __float_as_uint(fn.x);
            bfr[pb][ni][1] = __float_as_uint(fn.y);
        }
    };

    const int NSTAGE = K / BK;
    load_stage(0, 0);
    CP_COMMIT();

    #pragma unroll 1
    for (int s = 0; s < NSTAGE; s++) {
        CP_WAIT(0);
        __syncthreads();

        const float* Ab_s = Asf + (s & 1) * BM * XS;
        const float* Bb_s = Bsf + (s & 1) * BN * XS;

        // Load kk=0 fragments; next-stage cp.async issue fills the LDS shadow
        load_frag(Ab_s, Bb_s, 0, 0);
        if (s + 1 < NSTAGE) {
            load_stage(s + 1, (s + 1) & 1);
            CP_COMMIT();
        }

        #pragma unroll
        for (int kk = 0; kk < 4; kk++) {
            const int cur = kk & 1;
            if (kk < 3) load_frag(Ab_s, Bb_s, kk + 1, cur ^ 1);
            #pragma unroll
            for (int mi = 0; mi < 4; mi++)
                #pragma unroll
                for (int ni = 0; ni < 8; ni++)
                    mma_tf32(acc[mi][ni], afr[cur][mi], bfr[cur][ni]);
        }
    }

    // Epilogue
    #pragma unroll
    for (int mi = 0; mi < 4; mi++) {
        #pragma unroll
        for (int ni = 0; ni < 8; ni++) {
            const int row = mbase + wm0 + mi * 16 + gid;
            const int col = nbase + wn0 + ni * 8 + tig * 2;
            float2 v0 = make_float2(acc[mi][ni][0], acc[mi][ni][1]);
            float2 v1 = make_float2(acc[mi][ni][2], acc[mi][ni][3]);
            *(float2*)(C + (size_t)row * N + col)       = v0;
            *(float2*)(C + (size_t)(row + 8) * N + col) = v1;
        }
    }
}

// ---------------------------------------------------------------------------
// Elementwise tf32 round + K-permute, one 8-chunk per thread, float4 I/O.
// Permuted chunk = {k0,k4,k1,k5,k2,k6,k3,k7}.
// ---------------------------------------------------------------------------
__global__ void round_perm_kernel(const float4* __restrict__ in,
                                  float4* __restrict__ out, int n8)
{
    int i = blockIdx.x * blockDim.x + threadIdx.x;
    if (i < n8) {
        float4 a = in[2 * i];
        float4 b = in[2 * i + 1];
        float4 o0 = make_float4(to_tf32(a.x), to_tf32(b.x),
                                to_tf32(a.y), to_tf32(b.y));
        float4 o1 = make_float4(to_tf32(a.z), to_tf32(b.z),
                                to_tf32(a.w), to_tf32(b.w));
        out[2 * i]     = o0;
        out[2 * i + 1] = o1;
    }
}

// ---------------------------------------------------------------------------
// Transpose + tf32 round + K-permute: out[c][perm(r)] = tf32(in[r][c])
// ---------------------------------------------------------------------------
__global__ void transpose_kernel(const float* __restrict__ in,
                                 float* __restrict__ out, int R, int C)
{
    __shared__ float tile[32][33];
    int x = blockIdx.x * 32 + threadIdx.x;
    int y = blockIdx.y * 32 + threadIdx.y;
    #pragma unroll
    for (int j = 0; j < 32; j += 8)
        tile[threadIdx.y + j][threadIdx.x] = in[(size_t)(y + j) * C + x];
    __syncthreads();
    x = blockIdx.y * 32 + threadIdx.x;   // indexes R (the K dim) -> permute
    y = blockIdx.x * 32 + threadIdx.y;
    const int xp = permk(x);
    #pragma unroll
    for (int j = 0; j < 32; j += 8)
        out[(size_t)(y + j) * R + xp] = to_tf32(tile[threadIdx.x][threadIdx.y + j]);
}

// ---------------------------------------------------------------------------
// Local attention: one warp per (row, head). Output tf32 + K-permuted
// (it is GEMM2's A operand).
// ---------------------------------------------------------------------------
__global__ __launch_bounds__(256) void local_attn_kernel(
    const float* __restrict__ qkv, const float* __restrict__ bias,
    float* __restrict__ out)
{
    const int gw   = blockIdx.x * 8 + (threadIdx.x >> 5);
    const int lane = threadIdx.x & 31;
    const int r = gw >> 3;
    const int h = gw & 7;
    const int s = r & (SEQ - 1);

    const float* qrow = qkv + (size_t)r * QKV_N + h * DK;
    const float q0 = qrow[lane];
    const float q1 = qrow[lane + 32];

    float logit[KSIZE];
    #pragma unroll
    for (int w = 0; w < KSIZE; w++) {
        const int sn = s + w - NEIGH;
        float dot = 0.0f;
        if (sn >= 0 && sn < SEQ) {
            const float* krow = qkv + (size_t)(r + w - NEIGH) * QKV_N
                                + HEADS * DK + h * DK;
            float t = q0 * krow[lane] + q1 * krow[lane + 32];
            #pragma unroll
            for (int off = 16; off > 0; off >>= 1)
                t += __shfl_xor_sync(0xFFFFFFFFu, t, off);
            dot = t;
        }
        logit[w] = dot * 0.125f + bias[((size_t)h * SEQ + s) * KSIZE + w];
    }

    float m = logit[0];
    #pragma unroll
    for (int w = 1; w < KSIZE; w++) m = fmaxf(m, logit[w]);
    float p[KSIZE];
    float denom = 0.0f;
    #pragma unroll
    for (int w = 0; w < KSIZE; w++) {
        p[w] = expf(logit[w] - m);
        denom += p[w];
    }
    const float inv = 1.0f / denom;

    float o0 = 0.0f, o1 = 0.0f;
    #pragma unroll
    for (int w = 0; w < KSIZE; w++) {
        const int sn = s + w - NEIGH;
        if (sn >= 0 && sn < SEQ) {
            const float* vrow = qkv + (size_t)(r + w - NEIGH) * QKV_N
                                + 2 * HEADS * DK + h * DK;
            o0 += p[w] * vrow[lane];
            o1 += p[w] * vrow[lane + 32];
        }
    }
    float* orow = out + (size_t)r * DMODEL;
    orow[permk(h * DK + lane)]      = to_tf32(o0 * inv);
    orow[permk(h * DK + lane + 32)] = to_tf32(o1 * inv);
}

// ---------------------------------------------------------------------------
// Launch
// ---------------------------------------------------------------------------
extern "C" void kernel_launch(void* const* d_in, const int* in_sizes, int n_in,
                              void* d_out, int out_size)
{
    const float* x    = (const float*)d_in[0];  // [2,64,256,512]
    const float* bias = (const float*)d_in[1];  // [8,256,7]
    const float* Wqkv = (const float*)d_in[2];  // [512,1536]
    const float* Wout = (const float*)d_in[3];  // [512,512]
    float* out        = (float*)d_out;          // [32768,512]

    float *xt, *qkv, *att, *wqkvT, *woutT;
    cudaGetSymbolAddress((void**)&xt,    g_xt);
    cudaGetSymbolAddress((void**)&qkv,   g_qkv);
    cudaGetSymbolAddress((void**)&att,   g_att);
    cudaGetSymbolAddress((void**)&wqkvT, g_wqkvT);
    cudaGetSymbolAddress((void**)&woutT, g_woutT);

    const int dyn_smem = 2 * (BM + BN) * XS * (int)sizeof(float);  // 81920
    static bool attr_done = false;
    if (!attr_done) {
        cudaFuncSetAttribute(gemm_mma_tf32<DMODEL>,
                             cudaFuncAttributeMaxDynamicSharedMemorySize, dyn_smem);
        attr_done = true;
    }

    // 0) Pre-round+permute inputs / pre-transpose+round+permute weights
    {
        const int n8 = MROWS * DMODEL / 8;
        round_perm_kernel<<<(n8 + 255) / 256, 256>>>((const float4*)x,
                                                     (float4*)xt, n8);
        dim3 blk(32, 8);
        transpose_kernel<<<dim3(QKV_N / 32, DMODEL / 32), blk>>>(Wqkv, wqkvT,
                                                                 DMODEL, QKV_N);
        transpose_kernel<<<dim3(DMODEL / 32, DMODEL / 32), blk>>>(Wout, woutT,
                                                                  DMODEL, DMODEL);
    }

    // 1) QKV GEMM: [32768,512] @ [512,1536]
    {
        dim3 grid(QKV_N / BN, MROWS / BM);
        gemm_mma_tf32<DMODEL><<<grid, GEMM_THREADS, dyn_smem>>>(xt, wqkvT, qkv,
                                                                MROWS, QKV_N);
    }

    // 2) Local attention
    local_attn_kernel<<<MROWS, 256>>>(qkv, bias, att);

    // 3) Output GEMM: [32768,512] @ [512,512]
    {
        dim3 grid(DMODEL / BN, MROWS / BM);
        gemm_mma_tf32<DMODEL><<<grid, GEMM_THREADS, dyn_smem>>>(att, woutT, out,
                                                                MROWS, DMODEL);
    }
}

// round 9
// speedup vs baseline: 1.0111x; 1.0111x over previous
#include <cuda_runtime.h>
#include <cuda_bf16.h>
#include <math.h>
#include <stdint.h>

// Problem constants
#define BATCH   2
#define HW      64
#define SEQ     256
#define DMODEL  512
#define HEADS   8
#define DK      64
#define KSIZE   7
#define NEIGH   3

#define MROWS   (BATCH * HW * SEQ)      // 32768
#define QKV_N   (3 * HEADS * DK)        // 1536

// GEMM tiling: CTA 128x128, 8 warps @ 64x32 warp tile, 2 CTAs/SM (16 warps/SM)
#define BM 128
#define BN 128
#define BK 32
#define XS 40   // smem row stride (floats); XS mod 32 == 8 -> conflict-free LDS.64
#define GEMM_THREADS 256

// Scratch (allocation-free: __device__ globals)
__device__ float g_xt  [(size_t)MROWS * DMODEL];   //  64 MB (tf32, K-permuted)
__device__ float g_qkv [(size_t)MROWS * QKV_N];    // 201 MB
__device__ float g_att [(size_t)MROWS * DMODEL];   //  67 MB (tf32, K-permuted)
__device__ float g_wqkvT[(size_t)QKV_N * DMODEL];  //   3 MB (Wqkv^T, K-permuted)
__device__ float g_woutT[(size_t)DMODEL * DMODEL]; //   1 MB (Wout^T, K-permuted)

// ---------------------------------------------------------------------------
// Helpers
// ---------------------------------------------------------------------------
__device__ __forceinline__ float to_tf32(float x) {
    float y;
    asm("cvt.rna.tf32.f32 %0, %1;" : "=f"(y) : "f"(x));
    return y;
}

// In-8-chunk K permutation: k -> (k&~7) | ((k&3)<<1) | (k>>2&1).
// Applied to BOTH operands of each GEMM along K -> dot products invariant.
// Makes mma fragment k-pairs {t, t+4} adjacent in memory -> LDS.64.
__device__ __forceinline__ int permk(int k) {
    return (k & ~7) | ((k & 3) << 1) | ((k >> 2) & 1);
}

__device__ __forceinline__ uint32_t smem_u32(const void* p) {
    uint32_t a;
    asm("{ .reg .u64 t; cvta.to.shared.u64 t, %1; cvt.u32.u64 %0, t; }"
        : "=r"(a) : "l"(p));
    return a;
}

#define CP_ASYNC16(dst, src) \
    asm volatile("cp.async.cg.shared.global [%0], [%1], 16;" \
                 :: "r"(dst), "l"(src) : "memory")
#define CP_COMMIT() asm volatile("cp.async.commit_group;" ::: "memory")
#define CP_WAIT(n)  asm volatile("cp.async.wait_group %0;" :: "n"(n) : "memory")

__device__ __forceinline__ void mma_tf32(float* c, const uint32_t* a,
                                         const uint32_t* b) {
    asm volatile(
        "mma.sync.aligned.m16n8k8.row.col.f32.tf32.tf32.f32 "
        "{%0,%1,%2,%3}, {%4,%5,%6,%7}, {%8,%9}, {%0,%1,%2,%3};"
        : "+f"(c[0]), "+f"(c[1]), "+f"(c[2]), "+f"(c[3])
        : "r"(a[0]), "r"(a[1]), "r"(a[2]), "r"(a[3]),
          "r"(b[0]), "r"(b[1]));
}

// ---------------------------------------------------------------------------
// tf32 warp-MMA GEMM: C[M,N] = A[M,K] @ Bt[N,K]^T  (K-permuted operands)
// CTA 128x128, 256 threads, 8 warps @ 64x32 warp tile (2x4 warp grid).
// Double-buffered cp.async, BK=32, 2 CTAs/SM -> 16 warps/SM (4/SMSP).
// ONE __syncthreads per K-stage (barrier publishes stage s and protects
// buffer (s+1)&1, whose last reader was compute(s-1) before this barrier).
// ---------------------------------------------------------------------------
template<int K>
__global__ __launch_bounds__(GEMM_THREADS, 2) void gemm_mma_tf32(
    const float* __restrict__ A, const float* __restrict__ Bt,
    float* __restrict__ C, int M, int N)
{
    extern __shared__ float sm[];
    float* Asf = sm;                       // [2][BM][XS]
    float* Bsf = sm + 2 * BM * XS;         // [2][BN][XS]
    const uint32_t as_u = smem_u32(Asf);
    const uint32_t bs_u = smem_u32(Bsf);

    const int tid  = threadIdx.x;
    const int wid  = tid >> 5;
    const int lane = tid & 31;
    const int gid  = lane >> 2;    // 0..7
    const int tig  = lane & 3;     // 0..3

    const int wm0 = (wid >> 2) * 64;   // warp m-offset (0 or 64)
    const int wn0 = (wid & 3) * 32;    // warp n-offset (0,32,64,96)

    const int mbase = blockIdx.y * BM;
    const int nbase = blockIdx.x * BN;
    const float* Ab = A  + (size_t)mbase * K;
    const float* Bb = Bt + (size_t)nbase * K;

    const int lrow = tid >> 3;          // 0..31
    const int lk4  = (tid & 7) << 2;    // 0,4,...,28

    auto load_stage = [&](int s, int buf) {
        const float* Asrc = Ab + (size_t)s * BK;
        const float* Bsrc = Bb + (size_t)s * BK;
        #pragma unroll
        for (int j = 0; j < 4; j++) {
            int row = lrow + 32 * j;
            uint32_t d = as_u + (((uint32_t)(buf * BM + row) * XS + lk4) << 2);
            CP_ASYNC16(d, Asrc + (size_t)row * K + lk4);
        }
        #pragma unroll
        for (int j = 0; j < 4; j++) {
            int row = lrow + 32 * j;
            uint32_t d = bs_u + (((uint32_t)(buf * BN + row) * XS + lk4) << 2);
            CP_ASYNC16(d, Bsrc + (size_t)row * K + lk4);
        }
    };

    float acc[4][4][4];
    #pragma unroll
    for (int mi = 0; mi < 4; mi++)
        #pragma unroll
        for (int ni = 0; ni < 4; ni++)
            #pragma unroll
            for (int q = 0; q < 4; q++) acc[mi][ni][q] = 0.0f;

    const int NSTAGE = K / BK;
    load_stage(0, 0);
    CP_COMMIT();

    #pragma unroll 1
    for (int s = 0; s < NSTAGE; s++) {
        CP_WAIT(0);
        __syncthreads();

        if (s + 1 < NSTAGE) {
            load_stage(s + 1, (s + 1) & 1);
            CP_COMMIT();
        }

        const float* Ab_s = Asf + (s & 1) * BM * XS;
        const float* Bb_s = Bsf + (s & 1) * BN * XS;
        #pragma unroll
        for (int kk = 0; kk < 4; kk++) {
            const int k8 = kk * 8;
            uint32_t afr[4][4], bfr[4][2];
            #pragma unroll
            for (int mi = 0; mi < 4; mi++) {
                // K-permuted: {k=tig, k=tig+4} adjacent -> single LDS.64
                const float* r0 = Ab_s + (wm0 + mi * 16 + gid) * XS + k8 + 2 * tig;
                float2 f0 = *(const float2*)r0;
                float2 f8 = *(const float2*)(r0 + 8 * XS);
                afr[mi][0] = __float_as_uint(f0.x);
                afr[mi][1] = __float_as_uint(f8.x);
                afr[mi][2] = __float_as_uint(f0.y);
                afr[mi][3] = __float_as_uint(f8.y);
            }
            #pragma unroll
            for (int ni = 0; ni < 4; ni++) {
                const float* rn = Bb_s + (wn0 + ni * 8 + gid) * XS + k8 + 2 * tig;
                float2 fn = *(const float2*)rn;
                bfr[ni][0] = __float_as_uint(fn.x);
                bfr[ni][1] = __float_as_uint(fn.y);
            }
            #pragma unroll
            for (int mi = 0; mi < 4; mi++)
                #pragma unroll
                for (int ni = 0; ni < 4; ni++)
                    mma_tf32(acc[mi][ni], afr[mi], bfr[ni]);
        }
    }

    // Epilogue
    #pragma unroll
    for (int mi = 0; mi < 4; mi++) {
        #pragma unroll
        for (int ni = 0; ni < 4; ni++) {
            const int row = mbase + wm0 + mi * 16 + gid;
            const int col = nbase + wn0 + ni * 8 + tig * 2;
            float2 v0 = make_float2(acc[mi][ni][0], acc[mi][ni][1]);
            float2 v1 = make_float2(acc[mi][ni][2], acc[mi][ni][3]);
            *(float2*)(C + (size_t)row * N + col)       = v0;
            *(float2*)(C + (size_t)(row + 8) * N + col) = v1;
        }
    }
}

// ---------------------------------------------------------------------------
// Elementwise tf32 round + K-permute, one 8-chunk per thread, float4 I/O.
// Permuted chunk = {k0,k4,k1,k5,k2,k6,k3,k7}.
// ---------------------------------------------------------------------------
__global__ void round_perm_kernel(const float4* __restrict__ in,
                                  float4* __restrict__ out, int n8)
{
    int i = blockIdx.x * blockDim.x + threadIdx.x;
    if (i < n8) {
        float4 a = in[2 * i];
        float4 b = in[2 * i + 1];
        float4 o0 = make_float4(to_tf32(a.x), to_tf32(b.x),
                                to_tf32(a.y), to_tf32(b.y));
        float4 o1 = make_float4(to_tf32(a.z), to_tf32(b.z),
                                to_tf32(a.w), to_tf32(b.w));
        out[2 * i]     = o0;
        out[2 * i + 1] = o1;
    }
}

// ---------------------------------------------------------------------------
// Transpose + tf32 round + K-permute: out[c][perm(r)] = tf32(in[r][c])
// ---------------------------------------------------------------------------
__global__ void transpose_kernel(const float* __restrict__ in,
                                 float* __restrict__ out, int R, int C)
{
    __shared__ float tile[32][33];
    int x = blockIdx.x * 32 + threadIdx.x;
    int y = blockIdx.y * 32 + threadIdx.y;
    #pragma unroll
    for (int j = 0; j < 32; j += 8)
        tile[threadIdx.y + j][threadIdx.x] = in[(size_t)(y + j) * C + x];
    __syncthreads();
    x = blockIdx.y * 32 + threadIdx.x;   // indexes R (the K dim) -> permute
    y = blockIdx.x * 32 + threadIdx.y;
    const int xp = permk(x);
    #pragma unroll
    for (int j = 0; j < 32; j += 8)
        out[(size_t)(y + j) * R + xp] = to_tf32(tile[threadIdx.x][threadIdx.y + j]);
}

// ---------------------------------------------------------------------------
// Local attention: one warp per (row, head). Output tf32 + K-permuted
// (it is GEMM2's A operand).
// ---------------------------------------------------------------------------
__global__ __launch_bounds__(256) void local_attn_kernel(
    const float* __restrict__ qkv, const float* __restrict__ bias,
    float* __restrict__ out)
{
    const int gw   = blockIdx.x * 8 + (threadIdx.x >> 5);
    const int lane = threadIdx.x & 31;
    const int r = gw >> 3;
    const int h = gw & 7;
    const int s = r & (SEQ - 1);

    const float* qrow = qkv + (size_t)r * QKV_N + h * DK;
    const float q0 = qrow[lane];
    const float q1 = qrow[lane + 32];

    float logit[KSIZE];
    #pragma unroll
    for (int w = 0; w < KSIZE; w++) {
        const int sn = s + w - NEIGH;
        float dot = 0.0f;
        if (sn >= 0 && sn < SEQ) {
            const float* krow = qkv + (size_t)(r + w - NEIGH) * QKV_N
                                + HEADS * DK + h * DK;
            float t = q0 * krow[lane] + q1 * krow[lane + 32];
            #pragma unroll
            for (int off = 16; off > 0; off >>= 1)
                t += __shfl_xor_sync(0xFFFFFFFFu, t, off);
            dot = t;
        }
        logit[w] = dot * 0.125f + bias[((size_t)h * SEQ + s) * KSIZE + w];
    }

    float m = logit[0];
    #pragma unroll
    for (int w = 1; w < KSIZE; w++) m = fmaxf(m, logit[w]);
    float p[KSIZE];
    float denom = 0.0f;
    #pragma unroll
    for (int w = 0; w < KSIZE; w++) {
        p[w] = expf(logit[w] - m);
        denom += p[w];
    }
    const float inv = 1.0f / denom;

    float o0 = 0.0f, o1 = 0.0f;
    #pragma unroll
    for (int w = 0; w < KSIZE; w++) {
        const int sn = s + w - NEIGH;
        if (sn >= 0 && sn < SEQ) {
            const float* vrow = qkv + (size_t)(r + w - NEIGH) * QKV_N
                                + 2 * HEADS * DK + h * DK;
            o0 += p[w] * vrow[lane];
            o1 += p[w] * vrow[lane + 32];
        }
    }
    float* orow = out + (size_t)r * DMODEL;
    orow[permk(h * DK + lane)]      = to_tf32(o0 * inv);
    orow[permk(h * DK + lane + 32)] = to_tf32(o1 * inv);
}

// ---------------------------------------------------------------------------
// Launch
// ---------------------------------------------------------------------------
extern "C" void kernel_launch(void* const* d_in, const int* in_sizes, int n_in,
                              void* d_out, int out_size)
{
    const float* x    = (const float*)d_in[0];  // [2,64,256,512]
    const float* bias = (const float*)d_in[1];  // [8,256,7]
    const float* Wqkv = (const float*)d_in[2];  // [512,1536]
    const float* Wout = (const float*)d_in[3];  // [512,512]
    float* out        = (float*)d_out;          // [32768,512]

    float *xt, *qkv, *att, *wqkvT, *woutT;
    cudaGetSymbolAddress((void**)&xt,    g_xt);
    cudaGetSymbolAddress((void**)&qkv,   g_qkv);
    cudaGetSymbolAddress((void**)&att,   g_att);
    cudaGetSymbolAddress((void**)&wqkvT, g_wqkvT);
    cudaGetSymbolAddress((void**)&woutT, g_woutT);

    const int dyn_smem = 2 * (BM + BN) * XS * (int)sizeof(float);  // 81920
    static bool attr_done = false;
    if (!attr_done) {
        cudaFuncSetAttribute(gemm_mma_tf32<DMODEL>,
                             cudaFuncAttributeMaxDynamicSharedMemorySize, dyn_smem);
        attr_done = true;
    }

    // 0) Pre-round+permute inputs / pre-transpose+round+permute weights
    {
        const int n8 = MROWS * DMODEL / 8;
        round_perm_kernel<<<(n8 + 255) / 256, 256>>>((const float4*)x,
                                                     (float4*)xt, n8);
        dim3 blk(32, 8);
        transpose_kernel<<<dim3(QKV_N / 32, DMODEL / 32), blk>>>(Wqkv, wqkvT,
                                                                 DMODEL, QKV_N);
        transpose_kernel<<<dim3(DMODEL / 32, DMODEL / 32), blk>>>(Wout, woutT,
                                                                  DMODEL, DMODEL);
    }

    // 1) QKV GEMM: [32768,512] @ [512,1536]
    {
        dim3 grid(QKV_N / BN, MROWS / BM);
        gemm_mma_tf32<DMODEL><<<grid, GEMM_THREADS, dyn_smem>>>(xt, wqkvT, qkv,
                                                                MROWS, QKV_N);
    }

    // 2) Local attention
    local_attn_kernel<<<MROWS, 256>>>(qkv, bias, att);

    // 3) Output GEMM: [32768,512] @ [512,512]
    {
        dim3 grid(DMODEL / BN, MROWS / BM);
        gemm_mma_tf32<DMODEL><<<grid, GEMM_THREADS, dyn_smem>>>(att, woutT, out,
                                                                MROWS, DMODEL);
    }
}

// round 10
// speedup vs baseline: 1.0297x; 1.0183x over previous
#include <cuda_runtime.h>
#include <cuda_bf16.h>
#include <math.h>
#include <stdint.h>

// Problem constants
#define BATCH   2
#define HW      64
#define SEQ     256
#define DMODEL  512
#define HEADS   8
#define DK      64
#define KSIZE   7
#define NEIGH   3

#define MROWS   (BATCH * HW * SEQ)      // 32768
#define QKV_N   (3 * HEADS * DK)        // 1536

// GEMM tiling: CTA 128x128, 4 warps @ 64x64 warp tile (R6 pareto config)
#define BM 128
#define BN 128
#define BK 32
#define XS 40   // smem row stride (floats); XS mod 32 == 8 -> conflict-free LDS.64
#define GEMM_THREADS 128

// Scratch (allocation-free: __device__ globals)
__device__ float g_xt  [(size_t)MROWS * DMODEL];   //  64 MB (tf32, K-permuted)
__device__ float g_qkv [(size_t)MROWS * QKV_N];    // 201 MB
__device__ float g_att [(size_t)MROWS * DMODEL];   //  67 MB (tf32, K-permuted)
__device__ float g_wqkvT[(size_t)QKV_N * DMODEL];  //   3 MB (Wqkv^T, K-permuted)
__device__ float g_woutT[(size_t)DMODEL * DMODEL]; //   1 MB (Wout^T, K-permuted)

// ---------------------------------------------------------------------------
// Helpers
// ---------------------------------------------------------------------------
__device__ __forceinline__ float to_tf32(float x) {
    float y;
    asm("cvt.rna.tf32.f32 %0, %1;" : "=f"(y) : "f"(x));
    return y;
}

// In-8-chunk K permutation: k -> (k&~7) | ((k&3)<<1) | (k>>2&1).
// Applied to BOTH operands of each GEMM along K -> dot products invariant.
// Makes mma fragment k-pairs {t, t+4} adjacent in memory -> LDS.64.
__device__ __forceinline__ int permk(int k) {
    return (k & ~7) | ((k & 3) << 1) | ((k >> 2) & 1);
}

__device__ __forceinline__ uint32_t smem_u32(const void* p) {
    uint32_t a;
    asm("{ .reg .u64 t; cvta.to.shared.u64 t, %1; cvt.u32.u64 %0, t; }"
        : "=r"(a) : "l"(p));
    return a;
}

#define CP_ASYNC16(dst, src) \
    asm volatile("cp.async.cg.shared.global [%0], [%1], 16;" \
                 :: "r"(dst), "l"(src) : "memory")
#define CP_COMMIT() asm volatile("cp.async.commit_group;" ::: "memory")
#define CP_WAIT(n)  asm volatile("cp.async.wait_group %0;" :: "n"(n) : "memory")

__device__ __forceinline__ void mma_tf32(float* c, const uint32_t* a,
                                         const uint32_t* b) {
    asm volatile(
        "mma.sync.aligned.m16n8k8.row.col.f32.tf32.tf32.f32 "
        "{%0,%1,%2,%3}, {%4,%5,%6,%7}, {%8,%9}, {%0,%1,%2,%3};"
        : "+f"(c[0]), "+f"(c[1]), "+f"(c[2]), "+f"(c[3])
        : "r"(a[0]), "r"(a[1]), "r"(a[2]), "r"(a[3]),
          "r"(b[0]), "r"(b[1]));
}

// ---------------------------------------------------------------------------
// tf32 warp-MMA GEMM: C[M,N] = A[M,K] @ Bt[N,K]^T  (K-permuted operands)
// CTA 128x128, 128 threads, 4 warps @ 64x64 warp tile (2x2 warp grid).
// Double-buffered cp.async, BK=32, 2 CTAs/SM. One __syncthreads per K-stage.
// (R6 configuration: measured pareto point at tensor~58%.)
// ---------------------------------------------------------------------------
template<int K>
__global__ __launch_bounds__(GEMM_THREADS, 2) void gemm_mma_tf32(
    const float* __restrict__ A, const float* __restrict__ Bt,
    float* __restrict__ C, int M, int N)
{
    extern __shared__ float sm[];
    float* Asf = sm;                       // [2][BM][XS]
    float* Bsf = sm + 2 * BM * XS;         // [2][BN][XS]
    const uint32_t as_u = smem_u32(Asf);
    const uint32_t bs_u = smem_u32(Bsf);

    const int tid  = threadIdx.x;
    const int wid  = tid >> 5;
    const int lane = tid & 31;
    const int gid  = lane >> 2;    // 0..7
    const int tig  = lane & 3;     // 0..3

    const int wm0 = (wid >> 1) * 64;   // warp m-offset (0 or 64)
    const int wn0 = (wid & 1) * 64;    // warp n-offset (0 or 64)

    const int mbase = blockIdx.y * BM;
    const int nbase = blockIdx.x * BN;
    const float* Ab = A  + (size_t)mbase * K;
    const float* Bb = Bt + (size_t)nbase * K;

    const int lrow = tid >> 3;          // 0..15
    const int lk4  = (tid & 7) << 2;    // 0,4,...,28

    auto load_stage = [&](int s, int buf) {
        const float* Asrc = Ab + (size_t)s * BK;
        const float* Bsrc = Bb + (size_t)s * BK;
        #pragma unroll
        for (int j = 0; j < 8; j++) {
            int row = lrow + 16 * j;
            uint32_t d = as_u + (((uint32_t)(buf * BM + row) * XS + lk4) << 2);
            CP_ASYNC16(d, Asrc + (size_t)row * K + lk4);
        }
        #pragma unroll
        for (int j = 0; j < 8; j++) {
            int row = lrow + 16 * j;
            uint32_t d = bs_u + (((uint32_t)(buf * BN + row) * XS + lk4) << 2);
            CP_ASYNC16(d, Bsrc + (size_t)row * K + lk4);
        }
    };

    float acc[4][8][4];
    #pragma unroll
    for (int mi = 0; mi < 4; mi++)
        #pragma unroll
        for (int ni = 0; ni < 8; ni++)
            #pragma unroll
            for (int q = 0; q < 4; q++) acc[mi][ni][q] = 0.0f;

    const int NSTAGE = K / BK;
    load_stage(0, 0);
    CP_COMMIT();

    #pragma unroll 1
    for (int s = 0; s < NSTAGE; s++) {
        CP_WAIT(0);
        __syncthreads();

        if (s + 1 < NSTAGE) {
            load_stage(s + 1, (s + 1) & 1);
            CP_COMMIT();
        }

        const float* Ab_s = Asf + (s & 1) * BM * XS;
        const float* Bb_s = Bsf + (s & 1) * BN * XS;
        #pragma unroll
        for (int kk = 0; kk < 4; kk++) {
            const int k8 = kk * 8;
            uint32_t afr[4][4], bfr[8][2];
            #pragma unroll
            for (int mi = 0; mi < 4; mi++) {
                // K-permuted: {k=tig, k=tig+4} adjacent -> single LDS.64
                const float* r0 = Ab_s + (wm0 + mi * 16 + gid) * XS + k8 + 2 * tig;
                float2 f0 = *(const float2*)r0;
                float2 f8 = *(const float2*)(r0 + 8 * XS);
                afr[mi][0] = __float_as_uint(f0.x);
                afr[mi][1] = __float_as_uint(f8.x);
                afr[mi][2] = __float_as_uint(f0.y);
                afr[mi][3] = __float_as_uint(f8.y);
            }
            #pragma unroll
            for (int ni = 0; ni < 8; ni++) {
                const float* rn = Bb_s + (wn0 + ni * 8 + gid) * XS + k8 + 2 * tig;
                float2 fn = *(const float2*)rn;
                bfr[ni][0] = __float_as_uint(fn.x);
                bfr[ni][1] = __float_as_uint(fn.y);
            }
            #pragma unroll
            for (int mi = 0; mi < 4; mi++)
                #pragma unroll
                for (int ni = 0; ni < 8; ni++)
                    mma_tf32(acc[mi][ni], afr[mi], bfr[ni]);
        }
    }

    // Epilogue
    #pragma unroll
    for (int mi = 0; mi < 4; mi++) {
        #pragma unroll
        for (int ni = 0; ni < 8; ni++) {
            const int row = mbase + wm0 + mi * 16 + gid;
            const int col = nbase + wn0 + ni * 8 + tig * 2;
            float2 v0 = make_float2(acc[mi][ni][0], acc[mi][ni][1]);
            float2 v1 = make_float2(acc[mi][ni][2], acc[mi][ni][3]);
            *(float2*)(C + (size_t)row * N + col)       = v0;
            *(float2*)(C + (size_t)(row + 8) * N + col) = v1;
        }
    }
}

// ---------------------------------------------------------------------------
// Elementwise tf32 round + K-permute, one 8-chunk per thread, float4 I/O.
// Permuted chunk = {k0,k4,k1,k5,k2,k6,k3,k7}.
// ---------------------------------------------------------------------------
__global__ void round_perm_kernel(const float4* __restrict__ in,
                                  float4* __restrict__ out, int n8)
{
    int i = blockIdx.x * blockDim.x + threadIdx.x;
    if (i < n8) {
        float4 a = in[2 * i];
        float4 b = in[2 * i + 1];
        float4 o0 = make_float4(to_tf32(a.x), to_tf32(b.x),
                                to_tf32(a.y), to_tf32(b.y));
        float4 o1 = make_float4(to_tf32(a.z), to_tf32(b.z),
                                to_tf32(a.w), to_tf32(b.w));
        out[2 * i]     = o0;
        out[2 * i + 1] = o1;
    }
}

// ---------------------------------------------------------------------------
// Transpose + tf32 round + K-permute: out[c][perm(r)] = tf32(in[r][c])
// ---------------------------------------------------------------------------
__global__ void transpose_kernel(const float* __restrict__ in,
                                 float* __restrict__ out, int R, int C)
{
    __shared__ float tile[32][33];
    int x = blockIdx.x * 32 + threadIdx.x;
    int y = blockIdx.y * 32 + threadIdx.y;
    #pragma unroll
    for (int j = 0; j < 32; j += 8)
        tile[threadIdx.y + j][threadIdx.x] = in[(size_t)(y + j) * C + x];
    __syncthreads();
    x = blockIdx.y * 32 + threadIdx.x;   // indexes R (the K dim) -> permute
    y = blockIdx.x * 32 + threadIdx.y;
    const int xp = permk(x);
    #pragma unroll
    for (int j = 0; j < 32; j += 8)
        out[(size_t)(y + j) * R + xp] = to_tf32(tile[threadIdx.x][threadIdx.y + j]);
}

// ---------------------------------------------------------------------------
// Local attention: one warp per (row, head).
// LOCALITY REMAP: one block = 8 consecutive s-positions x ONE head, so the
// warps' 7-row k/v windows overlap (~7 KB unique per block instead of ~28 KB).
// block = ((bhw*HEADS + h)*SEQ/8 + sblk); warp w -> s = sblk*8 + w.
// ---------------------------------------------------------------------------
__global__ __launch_bounds__(256) void local_attn_kernel(
    const float* __restrict__ qkv, const float* __restrict__ bias,
    float* __restrict__ out)
{
    const int w    = threadIdx.x >> 5;
    const int lane = threadIdx.x & 31;
    const int sblk = blockIdx.x & (SEQ / 8 - 1);       // 0..31
    const int hh   = (blockIdx.x >> 5) & (HEADS - 1);  // head
    const int bhw  = blockIdx.x >> 8;                  // 0..127
    const int s = sblk * 8 + w;
    const int r = bhw * SEQ + s;
    const int h = hh;

    const float* qrow = qkv + (size_t)r * QKV_N + h * DK;
    const float q0 = qrow[lane];
    const float q1 = qrow[lane + 32];

    float logit[KSIZE];
    #pragma unroll
    for (int ww = 0; ww < KSIZE; ww++) {
        const int sn = s + ww - NEIGH;
        float dot = 0.0f;
        if (sn >= 0 && sn < SEQ) {
            const float* krow = qkv + (size_t)(r + ww - NEIGH) * QKV_N
                                + HEADS * DK + h * DK;
            float t = q0 * krow[lane] + q1 * krow[lane + 32];
            #pragma unroll
            for (int off = 16; off > 0; off >>= 1)
                t += __shfl_xor_sync(0xFFFFFFFFu, t, off);
            dot = t;
        }
        logit[ww] = dot * 0.125f + bias[((size_t)h * SEQ + s) * KSIZE + ww];
    }

    float m = logit[0];
    #pragma unroll
    for (int ww = 1; ww < KSIZE; ww++) m = fmaxf(m, logit[ww]);
    float p[KSIZE];
    float denom = 0.0f;
    #pragma unroll
    for (int ww = 0; ww < KSIZE; ww++) {
        p[ww] = __expf(logit[ww] - m);
        denom += p[ww];
    }
    const float inv = 1.0f / denom;

    float o0 = 0.0f, o1 = 0.0f;
    #pragma unroll
    for (int ww = 0; ww < KSIZE; ww++) {
        const int sn = s + ww - NEIGH;
        if (sn >= 0 && sn < SEQ) {
            const float* vrow = qkv + (size_t)(r + ww - NEIGH) * QKV_N
                                + 2 * HEADS * DK + h * DK;
            o0 += p[ww] * vrow[lane];
            o1 += p[ww] * vrow[lane + 32];
        }
    }
    float* orow = out + (size_t)r * DMODEL;
    orow[permk(h * DK + lane)]      = to_tf32(o0 * inv);
    orow[permk(h * DK + lane + 32)] = to_tf32(o1 * inv);
}

// ---------------------------------------------------------------------------
// Launch
// ---------------------------------------------------------------------------
extern "C" void kernel_launch(void* const* d_in, const int* in_sizes, int n_in,
                              void* d_out, int out_size)
{
    const float* x    = (const float*)d_in[0];  // [2,64,256,512]
    const float* bias = (const float*)d_in[1];  // [8,256,7]
    const float* Wqkv = (const float*)d_in[2];  // [512,1536]
    const float* Wout = (const float*)d_in[3];  // [512,512]
    float* out        = (float*)d_out;          // [32768,512]

    float *xt, *qkv, *att, *wqkvT, *woutT;
    cudaGetSymbolAddress((void**)&xt,    g_xt);
    cudaGetSymbolAddress((void**)&qkv,   g_qkv);
    cudaGetSymbolAddress((void**)&att,   g_att);
    cudaGetSymbolAddress((void**)&wqkvT, g_wqkvT);
    cudaGetSymbolAddress((void**)&woutT, g_woutT);

    const int dyn_smem = 2 * (BM + BN) * XS * (int)sizeof(float);  // 81920
    static bool attr_done = false;
    if (!attr_done) {
        cudaFuncSetAttribute(gemm_mma_tf32<DMODEL>,
                             cudaFuncAttributeMaxDynamicSharedMemorySize, dyn_smem);
        attr_done = true;
    }

    // 0) Pre-round+permute inputs / pre-transpose+round+permute weights
    {
        const int n8 = MROWS * DMODEL / 8;
        round_perm_kernel<<<(n8 + 255) / 256, 256>>>((const float4*)x,
                                                     (float4*)xt, n8);
        dim3 blk(32, 8);
        transpose_kernel<<<dim3(QKV_N / 32, DMODEL / 32), blk>>>(Wqkv, wqkvT,
                                                                 DMODEL, QKV_N);
        transpose_kernel<<<dim3(DMODEL / 32, DMODEL / 32), blk>>>(Wout, woutT,
                                                                  DMODEL, DMODEL);
    }

    // 1) QKV GEMM: [32768,512] @ [512,1536]
    {
        dim3 grid(QKV_N / BN, MROWS / BM);
        gemm_mma_tf32<DMODEL><<<grid, GEMM_THREADS, dyn_smem>>>(xt, wqkvT, qkv,
                                                                MROWS, QKV_N);
    }

    // 2) Local attention
    local_attn_kernel<<<MROWS, 256>>>(qkv, bias, att);

    // 3) Output GEMM: [32768,512] @ [512,512]
    {
        dim3 grid(DMODEL / BN, MROWS / BM);
        gemm_mma_tf32<DMODEL><<<grid, GEMM_THREADS, dyn_smem>>>(att, woutT, out,
                                                                MROWS, DMODEL);
    }
}

// round 11
// speedup vs baseline: 1.0717x; 1.0408x over previous
#include <cuda_runtime.h>
#include <cuda_bf16.h>
#include <math.h>
#include <stdint.h>

// Problem constants
#define BATCH   2
#define HW      64
#define SEQ     256
#define DMODEL  512
#define HEADS   8
#define DK      64
#define KSIZE   7
#define NEIGH   3

#define MROWS   (BATCH * HW * SEQ)      // 32768
#define QKV_N   (3 * HEADS * DK)        // 1536
#define NCHUNK  4
#define CHROWS  (MROWS / NCHUNK)        // 8192 rows = 32 sequences per chunk

// GEMM tiling: CTA 128x128, 4 warps @ 64x64 warp tile (pareto config)
#define BM 128
#define BN 128
#define BK 32
#define XS 40   // smem row stride (floats); XS mod 32 == 8 -> conflict-free LDS.64
#define GEMM_THREADS 128

// Scratch (allocation-free: __device__ globals)
__device__ float g_xt  [(size_t)MROWS * DMODEL];   //  64 MB (tf32, K-permuted)
__device__ float g_qkv [(size_t)MROWS * QKV_N];    // 201 MB
__device__ float g_att [(size_t)MROWS * DMODEL];   //  67 MB (tf32, K-permuted)
__device__ float g_wqkvT[(size_t)QKV_N * DMODEL];  //   3 MB (Wqkv^T, K-permuted)
__device__ float g_woutT[(size_t)DMODEL * DMODEL]; //   1 MB (Wout^T, K-permuted)

// ---------------------------------------------------------------------------
// Helpers
// ---------------------------------------------------------------------------
__device__ __forceinline__ float to_tf32(float x) {
    float y;
    asm("cvt.rna.tf32.f32 %0, %1;" : "=f"(y) : "f"(x));
    return y;
}

// In-8-chunk K permutation: k -> (k&~7) | ((k&3)<<1) | (k>>2&1).
// Applied to BOTH operands of each GEMM along K -> dot products invariant.
// Makes mma fragment k-pairs {t, t+4} adjacent in memory -> LDS.64.
__device__ __forceinline__ int permk(int k) {
    return (k & ~7) | ((k & 3) << 1) | ((k >> 2) & 1);
}

__device__ __forceinline__ uint32_t smem_u32(const void* p) {
    uint32_t a;
    asm("{ .reg .u64 t; cvta.to.shared.u64 t, %1; cvt.u32.u64 %0, t; }"
        : "=r"(a) : "l"(p));
    return a;
}

#define CP_ASYNC16(dst, src) \
    asm volatile("cp.async.cg.shared.global [%0], [%1], 16;" \
                 :: "r"(dst), "l"(src) : "memory")
#define CP_COMMIT() asm volatile("cp.async.commit_group;" ::: "memory")
#define CP_WAIT(n)  asm volatile("cp.async.wait_group %0;" :: "n"(n) : "memory")

__device__ __forceinline__ void mma_tf32(float* c, const uint32_t* a,
                                         const uint32_t* b) {
    asm volatile(
        "mma.sync.aligned.m16n8k8.row.col.f32.tf32.tf32.f32 "
        "{%0,%1,%2,%3}, {%4,%5,%6,%7}, {%8,%9}, {%0,%1,%2,%3};"
        : "+f"(c[0]), "+f"(c[1]), "+f"(c[2]), "+f"(c[3])
        : "r"(a[0]), "r"(a[1]), "r"(a[2]), "r"(a[3]),
          "r"(b[0]), "r"(b[1]));
}

// ---------------------------------------------------------------------------
// tf32 warp-MMA GEMM: C[M,N] = A[M,K] @ Bt[N,K]^T  (K-permuted operands)
// CTA 128x128, 128 threads, 4 warps @ 64x64 warp tile (2x2 warp grid).
// Double-buffered cp.async, BK=32, 2 CTAs/SM. One __syncthreads per K-stage.
// ---------------------------------------------------------------------------
template<int K>
__global__ __launch_bounds__(GEMM_THREADS, 2) void gemm_mma_tf32(
    const float* __restrict__ A, const float* __restrict__ Bt,
    float* __restrict__ C, int M, int N)
{
    extern __shared__ float sm[];
    float* Asf = sm;                       // [2][BM][XS]
    float* Bsf = sm + 2 * BM * XS;         // [2][BN][XS]
    const uint32_t as_u = smem_u32(Asf);
    const uint32_t bs_u = smem_u32(Bsf);

    const int tid  = threadIdx.x;
    const int wid  = tid >> 5;
    const int lane = tid & 31;
    const int gid  = lane >> 2;    // 0..7
    const int tig  = lane & 3;     // 0..3

    const int wm0 = (wid >> 1) * 64;   // warp m-offset (0 or 64)
    const int wn0 = (wid & 1) * 64;    // warp n-offset (0 or 64)

    const int mbase = blockIdx.y * BM;
    const int nbase = blockIdx.x * BN;
    const float* Ab = A  + (size_t)mbase * K;
    const float* Bb = Bt + (size_t)nbase * K;

    const int lrow = tid >> 3;          // 0..15
    const int lk4  = (tid & 7) << 2;    // 0,4,...,28

    auto load_stage = [&](int s, int buf) {
        const float* Asrc = Ab + (size_t)s * BK;
        const float* Bsrc = Bb + (size_t)s * BK;
        #pragma unroll
        for (int j = 0; j < 8; j++) {
            int row = lrow + 16 * j;
            uint32_t d = as_u + (((uint32_t)(buf * BM + row) * XS + lk4) << 2);
            CP_ASYNC16(d, Asrc + (size_t)row * K + lk4);
        }
        #pragma unroll
        for (int j = 0; j < 8; j++) {
            int row = lrow + 16 * j;
            uint32_t d = bs_u + (((uint32_t)(buf * BN + row) * XS + lk4) << 2);
            CP_ASYNC16(d, Bsrc + (size_t)row * K + lk4);
        }
    };

    float acc[4][8][4];
    #pragma unroll
    for (int mi = 0; mi < 4; mi++)
        #pragma unroll
        for (int ni = 0; ni < 8; ni++)
            #pragma unroll
            for (int q = 0; q < 4; q++) acc[mi][ni][q] = 0.0f;

    const int NSTAGE = K / BK;
    load_stage(0, 0);
    CP_COMMIT();

    #pragma unroll 1
    for (int s = 0; s < NSTAGE; s++) {
        CP_WAIT(0);
        __syncthreads();

        if (s + 1 < NSTAGE) {
            load_stage(s + 1, (s + 1) & 1);
            CP_COMMIT();
        }

        const float* Ab_s = Asf + (s & 1) * BM * XS;
        const float* Bb_s = Bsf + (s & 1) * BN * XS;
        #pragma unroll
        for (int kk = 0; kk < 4; kk++) {
            const int k8 = kk * 8;
            uint32_t afr[4][4], bfr[8][2];
            #pragma unroll
            for (int mi = 0; mi < 4; mi++) {
                // K-permuted: {k=tig, k=tig+4} adjacent -> single LDS.64
                const float* r0 = Ab_s + (wm0 + mi * 16 + gid) * XS + k8 + 2 * tig;
                float2 f0 = *(const float2*)r0;
                float2 f8 = *(const float2*)(r0 + 8 * XS);
                afr[mi][0] = __float_as_uint(f0.x);
                afr[mi][1] = __float_as_uint(f8.x);
                afr[mi][2] = __float_as_uint(f0.y);
                afr[mi][3] = __float_as_uint(f8.y);
            }
            #pragma unroll
            for (int ni = 0; ni < 8; ni++) {
                const float* rn = Bb_s + (wn0 + ni * 8 + gid) * XS + k8 + 2 * tig;
                float2 fn = *(const float2*)rn;
                bfr[ni][0] = __float_as_uint(fn.x);
                bfr[ni][1] = __float_as_uint(fn.y);
            }
            #pragma unroll
            for (int mi = 0; mi < 4; mi++)
                #pragma unroll
                for (int ni = 0; ni < 8; ni++)
                    mma_tf32(acc[mi][ni], afr[mi], bfr[ni]);
        }
    }

    // Epilogue
    #pragma unroll
    for (int mi = 0; mi < 4; mi++) {
        #pragma unroll
        for (int ni = 0; ni < 8; ni++) {
            const int row = mbase + wm0 + mi * 16 + gid;
            const int col = nbase + wn0 + ni * 8 + tig * 2;
            float2 v0 = make_float2(acc[mi][ni][0], acc[mi][ni][1]);
            float2 v1 = make_float2(acc[mi][ni][2], acc[mi][ni][3]);
            *(float2*)(C + (size_t)row * N + col)       = v0;
            *(float2*)(C + (size_t)(row + 8) * N + col) = v1;
        }
    }
}

// ---------------------------------------------------------------------------
// Elementwise tf32 round + K-permute, one 8-chunk per thread, float4 I/O.
// Permuted chunk = {k0,k4,k1,k5,k2,k6,k3,k7}.
// ---------------------------------------------------------------------------
__global__ void round_perm_kernel(const float4* __restrict__ in,
                                  float4* __restrict__ out, int n8)
{
    int i = blockIdx.x * blockDim.x + threadIdx.x;
    if (i < n8) {
        float4 a = in[2 * i];
        float4 b = in[2 * i + 1];
        float4 o0 = make_float4(to_tf32(a.x), to_tf32(b.x),
                                to_tf32(a.y), to_tf32(b.y));
        float4 o1 = make_float4(to_tf32(a.z), to_tf32(b.z),
                                to_tf32(a.w), to_tf32(b.w));
        out[2 * i]     = o0;
        out[2 * i + 1] = o1;
    }
}

// ---------------------------------------------------------------------------
// Transpose + tf32 round + K-permute: out[c][perm(r)] = tf32(in[r][c])
// ---------------------------------------------------------------------------
__global__ void transpose_kernel(const float* __restrict__ in,
                                 float* __restrict__ out, int R, int C)
{
    __shared__ float tile[32][33];
    int x = blockIdx.x * 32 + threadIdx.x;
    int y = blockIdx.y * 32 + threadIdx.y;
    #pragma unroll
    for (int j = 0; j < 32; j += 8)
        tile[threadIdx.y + j][threadIdx.x] = in[(size_t)(y + j) * C + x];
    __syncthreads();
    x = blockIdx.y * 32 + threadIdx.x;   // indexes R (the K dim) -> permute
    y = blockIdx.x * 32 + threadIdx.y;
    const int xp = permk(x);
    #pragma unroll
    for (int j = 0; j < 32; j += 8)
        out[(size_t)(y + j) * R + xp] = to_tf32(tile[threadIdx.x][threadIdx.y + j]);
}

// ---------------------------------------------------------------------------
// Local attention: one warp per (row, head); one block = 8 consecutive s x
// one head (locality remap). Pointers are per-chunk; bias is global
// (depends only on h,s).
// ---------------------------------------------------------------------------
__global__ __launch_bounds__(256) void local_attn_kernel(
    const float* __restrict__ qkv, const float* __restrict__ bias,
    float* __restrict__ out)
{
    const int w    = threadIdx.x >> 5;
    const int lane = threadIdx.x & 31;
    const int sblk = blockIdx.x & (SEQ / 8 - 1);       // 0..31
    const int h    = (blockIdx.x >> 5) & (HEADS - 1);  // head
    const int bhw  = blockIdx.x >> 8;                  // local sequence index
    const int s = sblk * 8 + w;
    const int r = bhw * SEQ + s;

    const float* qrow = qkv + (size_t)r * QKV_N + h * DK;
    const float q0 = qrow[lane];
    const float q1 = qrow[lane + 32];

    float logit[KSIZE];
    #pragma unroll
    for (int ww = 0; ww < KSIZE; ww++) {
        const int sn = s + ww - NEIGH;
        float dot = 0.0f;
        if (sn >= 0 && sn < SEQ) {
            const float* krow = qkv + (size_t)(r + ww - NEIGH) * QKV_N
                                + HEADS * DK + h * DK;
            float t = q0 * krow[lane] + q1 * krow[lane + 32];
            #pragma unroll
            for (int off = 16; off > 0; off >>= 1)
                t += __shfl_xor_sync(0xFFFFFFFFu, t, off);
            dot = t;
        }
        logit[ww] = dot * 0.125f + bias[((size_t)h * SEQ + s) * KSIZE + ww];
    }

    float m = logit[0];
    #pragma unroll
    for (int ww = 1; ww < KSIZE; ww++) m = fmaxf(m, logit[ww]);
    float p[KSIZE];
    float denom = 0.0f;
    #pragma unroll
    for (int ww = 0; ww < KSIZE; ww++) {
        p[ww] = __expf(logit[ww] - m);
        denom += p[ww];
    }
    const float inv = 1.0f / denom;

    float o0 = 0.0f, o1 = 0.0f;
    #pragma unroll
    for (int ww = 0; ww < KSIZE; ww++) {
        const int sn = s + ww - NEIGH;
        if (sn >= 0 && sn < SEQ) {
            const float* vrow = qkv + (size_t)(r + ww - NEIGH) * QKV_N
                                + 2 * HEADS * DK + h * DK;
            o0 += p[ww] * vrow[lane];
            o1 += p[ww] * vrow[lane + 32];
        }
    }
    float* orow = out + (size_t)r * DMODEL;
    orow[permk(h * DK + lane)]      = to_tf32(o0 * inv);
    orow[permk(h * DK + lane + 32)] = to_tf32(o1 * inv);
}

// ---------------------------------------------------------------------------
// Launch: 4 row-chunks (32 sequences each, halo never crosses a chunk)
// pipelined across 2 streams. Fork after the shared weight transposes,
// join on the default stream. Pure overlap: attention/round (memory-bound)
// co-run with the other stream's GEMM (tensor-bound); GEMM tails filled.
// ---------------------------------------------------------------------------
extern "C" void kernel_launch(void* const* d_in, const int* in_sizes, int n_in,
                              void* d_out, int out_size)
{
    const float* x    = (const float*)d_in[0];  // [2,64,256,512]
    const float* bias = (const float*)d_in[1];  // [8,256,7]
    const float* Wqkv = (const float*)d_in[2];  // [512,1536]
    const float* Wout = (const float*)d_in[3];  // [512,512]
    float* out        = (float*)d_out;          // [32768,512]

    float *xt, *qkv, *att, *wqkvT, *woutT;
    cudaGetSymbolAddress((void**)&xt,    g_xt);
    cudaGetSymbolAddress((void**)&qkv,   g_qkv);
    cudaGetSymbolAddress((void**)&att,   g_att);
    cudaGetSymbolAddress((void**)&wqkvT, g_wqkvT);
    cudaGetSymbolAddress((void**)&woutT, g_woutT);

    const int dyn_smem = 2 * (BM + BN) * XS * (int)sizeof(float);  // 81920

    static cudaStream_t st[2] = {nullptr, nullptr};
    static cudaEvent_t evFork = nullptr;
    static cudaEvent_t evJoin[2] = {nullptr, nullptr};
    static bool init_done = false;
    if (!init_done) {
        cudaFuncSetAttribute(gemm_mma_tf32<DMODEL>,
                             cudaFuncAttributeMaxDynamicSharedMemorySize, dyn_smem);
        cudaStreamCreateWithFlags(&st[0], cudaStreamNonBlocking);
        cudaStreamCreateWithFlags(&st[1], cudaStreamNonBlocking);
        cudaEventCreateWithFlags(&evFork,    cudaEventDisableTiming);
        cudaEventCreateWithFlags(&evJoin[0], cudaEventDisableTiming);
        cudaEventCreateWithFlags(&evJoin[1], cudaEventDisableTiming);
        init_done = true;
    }

    // Shared prep on the (captured) default stream
    {
        dim3 blk(32, 8);
        transpose_kernel<<<dim3(QKV_N / 32, DMODEL / 32), blk>>>(Wqkv, wqkvT,
                                                                 DMODEL, QKV_N);
        transpose_kernel<<<dim3(DMODEL / 32, DMODEL / 32), blk>>>(Wout, woutT,
                                                                  DMODEL, DMODEL);
    }
    cudaEventRecord(evFork, 0);
    cudaStreamWaitEvent(st[0], evFork, 0);
    cudaStreamWaitEvent(st[1], evFork, 0);

    // Chunked pipeline: round -> GEMM1 -> attention -> GEMM2 per chunk
    for (int c = 0; c < NCHUNK; c++) {
        cudaStream_t s = st[c & 1];
        const size_t ro = (size_t)c * CHROWS;
        const float* xc  = x   + ro * DMODEL;
        float* xtc       = xt  + ro * DMODEL;
        float* qkvc      = qkv + ro * QKV_N;
        float* attc      = att + ro * DMODEL;
        float* outc      = out + ro * DMODEL;

        const int n8 = CHROWS * DMODEL / 8;
        round_perm_kernel<<<(n8 + 255) / 256, 256, 0, s>>>(
            (const float4*)xc, (float4*)xtc, n8);

        gemm_mma_tf32<DMODEL><<<dim3(QKV_N / BN, CHROWS / BM),
                                GEMM_THREADS, dyn_smem, s>>>(
            xtc, wqkvT, qkvc, CHROWS, QKV_N);

        local_attn_kernel<<<CHROWS, 256, 0, s>>>(qkvc, bias, attc);

        gemm_mma_tf32<DMODEL><<<dim3(DMODEL / BN, CHROWS / BM),
                                GEMM_THREADS, dyn_smem, s>>>(
            attc, woutT, outc, CHROWS, DMODEL);
    }

    cudaEventRecord(evJoin[0], st[0]);
    cudaEventRecord(evJoin[1], st[1]);
    cudaStreamWaitEvent(0, evJoin[0], 0);
    cudaStreamWaitEvent(0, evJoin[1], 0);
}

// round 12
// speedup vs baseline: 1.6310x; 1.5220x over previous
#include <cuda_runtime.h>
#include <cuda_fp16.h>
#include <cuda_bf16.h>
#include <math.h>
#include <stdint.h>

// Problem constants
#define BATCH   2
#define HW      64
#define SEQ     256
#define DMODEL  512
#define HEADS   8
#define DK      64
#define KSIZE   7
#define NEIGH   3

#define MROWS   (BATCH * HW * SEQ)      // 32768
#define QKV_N   (3 * HEADS * DK)        // 1536
#define NCHUNK  4
#define CHROWS  (MROWS / NCHUNK)        // 8192 rows

// GEMM tiling: CTA 128x128, 4 warps @ 64x64 warp tile, fp16 m16n8k16
#define BM 128
#define BN 128
#define BKH 64   // K-tile in halves
#define XSH 80   // smem row stride in halves (160B; word-stride 40 == 8 mod 32)
#define GEMM_THREADS 128

// Scratch (allocation-free: __device__ globals)
__device__ __half g_xt  [(size_t)MROWS * DMODEL];   //  32 MB (fp16, K-perm16)
__device__ float  g_qkv [(size_t)MROWS * QKV_N];    // 201 MB
__device__ __half g_att [(size_t)MROWS * DMODEL];   //  32 MB (fp16, K-perm16)
__device__ __half g_wqkvT[(size_t)QKV_N * DMODEL];  // 1.5 MB (Wqkv^T, perm16)
__device__ __half g_woutT[(size_t)DMODEL * DMODEL]; // 0.5 MB (Wout^T, perm16)

// ---------------------------------------------------------------------------
// Helpers
// ---------------------------------------------------------------------------
// 16-chunk K permutation: pair p=(k>>1)&7 -> p'=((p&3)<<1)|(p>>2), keep k&1.
// pos_local(k) = ((k>>1)&3)<<2 | ((k>>3)&1)<<1 | (k&1)
// Fragment k-quads {2t,2t+1,8+2t,8+2t+1} become 4 consecutive halves -> LDS.64.
__device__ __host__ __forceinline__ int perm16(int k) {
    return (k & ~15) | (((k >> 1) & 3) << 2) | (((k >> 3) & 1) << 1) | (k & 1);
}

__device__ __forceinline__ uint32_t smem_u32(const void* p) {
    uint32_t a;
    asm("{ .reg .u64 t; cvta.to.shared.u64 t, %1; cvt.u32.u64 %0, t; }"
        : "=r"(a) : "l"(p));
    return a;
}

#define CP_ASYNC16(dst, src) \
    asm volatile("cp.async.cg.shared.global [%0], [%1], 16;" \
                 :: "r"(dst), "l"(src) : "memory")
#define CP_COMMIT() asm volatile("cp.async.commit_group;" ::: "memory")
#define CP_WAIT(n)  asm volatile("cp.async.wait_group %0;" :: "n"(n) : "memory")

__device__ __forceinline__ void mma_f16(float* c, const uint32_t* a,
                                        const uint32_t* b) {
    asm volatile(
        "mma.sync.aligned.m16n8k16.row.col.f32.f16.f16.f32 "
        "{%0,%1,%2,%3}, {%4,%5,%6,%7}, {%8,%9}, {%0,%1,%2,%3};"
        : "+f"(c[0]), "+f"(c[1]), "+f"(c[2]), "+f"(c[3])
        : "r"(a[0]), "r"(a[1]), "r"(a[2]), "r"(a[3]),
          "r"(b[0]), "r"(b[1]));
}

// ---------------------------------------------------------------------------
// fp16 warp-MMA GEMM: C[M,N] = A[M,K] @ Bt[N,K]^T  (perm16 K layout)
// CTA 128x128, 4 warps @ 64x64, BK=64 halves, double-buffered cp.async,
// 2 CTAs/SM, one __syncthreads per K-stage. All fragment loads are LDS.64,
// conflict-free (row word-stride 40 == 8 mod 32).
// ---------------------------------------------------------------------------
template<int K>
__global__ __launch_bounds__(GEMM_THREADS, 2) void gemm_mma_f16(
    const __half* __restrict__ A, const __half* __restrict__ Bt,
    float* __restrict__ C, int M, int N)
{
    extern __shared__ __half smh[];
    __half* Asf = smh;                       // [2][BM][XSH]
    __half* Bsf = smh + 2 * BM * XSH;        // [2][BN][XSH]
    const uint32_t as_u = smem_u32(Asf);
    const uint32_t bs_u = smem_u32(Bsf);

    const int tid  = threadIdx.x;
    const int wid  = tid >> 5;
    const int lane = tid & 31;
    const int gid  = lane >> 2;    // 0..7
    const int tig  = lane & 3;     // 0..3

    const int wm0 = (wid >> 1) * 64;   // warp m-offset (0 or 64)
    const int wn0 = (wid & 1) * 64;    // warp n-offset (0 or 64)

    const int mbase = blockIdx.y * BM;
    const int nbase = blockIdx.x * BN;
    const __half* Ab = A  + (size_t)mbase * K;
    const __half* Bb = Bt + (size_t)nbase * K;

    const int lrow = tid >> 3;          // 0..15
    const int lk8  = (tid & 7) << 3;    // 0,8,...,56 halves (16B each)

    auto load_stage = [&](int s, int buf) {
        const __half* Asrc = Ab + (size_t)s * BKH;
        const __half* Bsrc = Bb + (size_t)s * BKH;
        #pragma unroll
        for (int j = 0; j < 8; j++) {
            int row = lrow + 16 * j;
            uint32_t d = as_u + (((uint32_t)(buf * BM + row) * XSH + lk8) << 1);
            CP_ASYNC16(d, Asrc + (size_t)row * K + lk8);
        }
        #pragma unroll
        for (int j = 0; j < 8; j++) {
            int row = lrow + 16 * j;
            uint32_t d = bs_u + (((uint32_t)(buf * BN + row) * XSH + lk8) << 1);
            CP_ASYNC16(d, Bsrc + (size_t)row * K + lk8);
        }
    };

    float acc[4][8][4];
    #pragma unroll
    for (int mi = 0; mi < 4; mi++)
        #pragma unroll
        for (int ni = 0; ni < 8; ni++)
            #pragma unroll
            for (int q = 0; q < 4; q++) acc[mi][ni][q] = 0.0f;

    const int NSTAGE = K / BKH;   // 8
    load_stage(0, 0);
    CP_COMMIT();

    #pragma unroll 1
    for (int s = 0; s < NSTAGE; s++) {
        CP_WAIT(0);
        __syncthreads();

        if (s + 1 < NSTAGE) {
            load_stage(s + 1, (s + 1) & 1);
            CP_COMMIT();
        }

        const __half* Ab_s = Asf + (s & 1) * BM * XSH;
        const __half* Bb_s = Bsf + (s & 1) * BN * XSH;
        #pragma unroll
        for (int kk = 0; kk < 4; kk++) {
            const int k16 = kk * 16 + 4 * tig;
            uint32_t afr[4][4], bfr[8][2];
            #pragma unroll
            for (int mi = 0; mi < 4; mi++) {
                const __half* r0 = Ab_s + (wm0 + mi * 16 + gid) * XSH + k16;
                uint2 u0 = *(const uint2*)r0;
                uint2 u8 = *(const uint2*)(r0 + 8 * XSH);
                afr[mi][0] = u0.x;   // (g,   k 2t,2t+1)
                afr[mi][1] = u8.x;   // (g+8, k 2t,2t+1)
                afr[mi][2] = u0.y;   // (g,   k 8+2t,8+2t+1)
                afr[mi][3] = u8.y;   // (g+8, k 8+2t,8+2t+1)
            }
            #pragma unroll
            for (int ni = 0; ni < 8; ni++) {
                const __half* rn = Bb_s + (wn0 + ni * 8 + gid) * XSH + k16;
                uint2 u = *(const uint2*)rn;
                bfr[ni][0] = u.x;
                bfr[ni][1] = u.y;
            }
            #pragma unroll
            for (int mi = 0; mi < 4; mi++)
                #pragma unroll
                for (int ni = 0; ni < 8; ni++)
                    mma_f16(acc[mi][ni], afr[mi], bfr[ni]);
        }
    }

    // Epilogue (C layout identical to m16n8k8)
    #pragma unroll
    for (int mi = 0; mi < 4; mi++) {
        #pragma unroll
        for (int ni = 0; ni < 8; ni++) {
            const int row = mbase + wm0 + mi * 16 + gid;
            const int col = nbase + wn0 + ni * 8 + tig * 2;
            float2 v0 = make_float2(acc[mi][ni][0], acc[mi][ni][1]);
            float2 v1 = make_float2(acc[mi][ni][2], acc[mi][ni][3]);
            *(float2*)(C + (size_t)row * N + col)       = v0;
            *(float2*)(C + (size_t)(row + 8) * N + col) = v1;
        }
    }
}

// ---------------------------------------------------------------------------
// fp32 -> fp16 convert + perm16, one 16-chunk per thread.
// ---------------------------------------------------------------------------
__global__ void conv_perm_kernel(const float4* __restrict__ in,
                                 __half* __restrict__ out, int n16)
{
    int i = blockIdx.x * blockDim.x + threadIdx.x;
    if (i < n16) {
        float4 f0 = in[4 * i + 0];
        float4 f1 = in[4 * i + 1];
        float4 f2 = in[4 * i + 2];
        float4 f3 = in[4 * i + 3];
        float v[16] = {f0.x, f0.y, f0.z, f0.w, f1.x, f1.y, f1.z, f1.w,
                       f2.x, f2.y, f2.z, f2.w, f3.x, f3.y, f3.z, f3.w};
        __half h[16];
        #pragma unroll
        for (int k = 0; k < 16; k++) {
            const int pos = (((k >> 1) & 3) << 2) | (((k >> 3) & 1) << 1) | (k & 1);
            h[pos] = __float2half_rn(v[k]);
        }
        uint4* dst = (uint4*)(out + 16 * (size_t)i);
        dst[0] = *(uint4*)(h);
        dst[1] = *(uint4*)(h + 8);
    }
}

// ---------------------------------------------------------------------------
// Transpose + fp16 + perm16: out[c][perm16(r)] = half(in[r][c])
// ---------------------------------------------------------------------------
__global__ void transpose_kernel(const float* __restrict__ in,
                                 __half* __restrict__ out, int R, int C)
{
    __shared__ float tile[32][33];
    int x = blockIdx.x * 32 + threadIdx.x;
    int y = blockIdx.y * 32 + threadIdx.y;
    #pragma unroll
    for (int j = 0; j < 32; j += 8)
        tile[threadIdx.y + j][threadIdx.x] = in[(size_t)(y + j) * C + x];
    __syncthreads();
    x = blockIdx.y * 32 + threadIdx.x;   // indexes R (the K dim) -> permute
    y = blockIdx.x * 32 + threadIdx.y;
    const int xp = perm16(x);
    #pragma unroll
    for (int j = 0; j < 32; j += 8)
        out[(size_t)(y + j) * R + xp] =
            __float2half_rn(tile[threadIdx.x][threadIdx.y + j]);
}

// ---------------------------------------------------------------------------
// Local attention: one warp per (row, head); block = 8 consecutive s x one
// head. qkv fp32 in; att fp16 (perm16) out.
// ---------------------------------------------------------------------------
__global__ __launch_bounds__(256) void local_attn_kernel(
    const float* __restrict__ qkv, const float* __restrict__ bias,
    __half* __restrict__ out)
{
    const int w    = threadIdx.x >> 5;
    const int lane = threadIdx.x & 31;
    const int sblk = blockIdx.x & (SEQ / 8 - 1);
    const int h    = (blockIdx.x >> 5) & (HEADS - 1);
    const int bhw  = blockIdx.x >> 8;
    const int s = sblk * 8 + w;
    const int r = bhw * SEQ + s;

    const float* qrow = qkv + (size_t)r * QKV_N + h * DK;
    const float q0 = qrow[lane];
    const float q1 = qrow[lane + 32];

    float logit[KSIZE];
    #pragma unroll
    for (int ww = 0; ww < KSIZE; ww++) {
        const int sn = s + ww - NEIGH;
        float dot = 0.0f;
        if (sn >= 0 && sn < SEQ) {
            const float* krow = qkv + (size_t)(r + ww - NEIGH) * QKV_N
                                + HEADS * DK + h * DK;
            float t = q0 * krow[lane] + q1 * krow[lane + 32];
            #pragma unroll
            for (int off = 16; off > 0; off >>= 1)
                t += __shfl_xor_sync(0xFFFFFFFFu, t, off);
            dot = t;
        }
        logit[ww] = dot * 0.125f + bias[((size_t)h * SEQ + s) * KSIZE + ww];
    }

    float m = logit[0];
    #pragma unroll
    for (int ww = 1; ww < KSIZE; ww++) m = fmaxf(m, logit[ww]);
    float p[KSIZE];
    float denom = 0.0f;
    #pragma unroll
    for (int ww = 0; ww < KSIZE; ww++) {
        p[ww] = __expf(logit[ww] - m);
        denom += p[ww];
    }
    const float inv = 1.0f / denom;

    float o0 = 0.0f, o1 = 0.0f;
    #pragma unroll
    for (int ww = 0; ww < KSIZE; ww++) {
        const int sn = s + ww - NEIGH;
        if (sn >= 0 && sn < SEQ) {
            const float* vrow = qkv + (size_t)(r + ww - NEIGH) * QKV_N
                                + 2 * HEADS * DK + h * DK;
            o0 += p[ww] * vrow[lane];
            o1 += p[ww] * vrow[lane + 32];
        }
    }
    __half* orow = out + (size_t)r * DMODEL;
    orow[perm16(h * DK + lane)]      = __float2half_rn(o0 * inv);
    orow[perm16(h * DK + lane + 32)] = __float2half_rn(o1 * inv);
}

// ---------------------------------------------------------------------------
// Launch: 4 row-chunks pipelined across 2 streams (halo never crosses a
// chunk boundary: chunks are whole (b,hw) sequences).
// ---------------------------------------------------------------------------
extern "C" void kernel_launch(void* const* d_in, const int* in_sizes, int n_in,
                              void* d_out, int out_size)
{
    const float* x    = (const float*)d_in[0];  // [2,64,256,512]
    const float* bias = (const float*)d_in[1];  // [8,256,7]
    const float* Wqkv = (const float*)d_in[2];  // [512,1536]
    const float* Wout = (const float*)d_in[3];  // [512,512]
    float* out        = (float*)d_out;          // [32768,512]

    __half *xt, *att, *wqkvT, *woutT;
    float *qkv;
    cudaGetSymbolAddress((void**)&xt,    g_xt);
    cudaGetSymbolAddress((void**)&qkv,   g_qkv);
    cudaGetSymbolAddress((void**)&att,   g_att);
    cudaGetSymbolAddress((void**)&wqkvT, g_wqkvT);
    cudaGetSymbolAddress((void**)&woutT, g_woutT);

    const int dyn_smem = 2 * (BM + BN) * XSH * (int)sizeof(__half);  // 81920

    static cudaStream_t st[2] = {nullptr, nullptr};
    static cudaEvent_t evFork = nullptr;
    static cudaEvent_t evJoin[2] = {nullptr, nullptr};
    static bool init_done = false;
    if (!init_done) {
        cudaFuncSetAttribute(gemm_mma_f16<DMODEL>,
                             cudaFuncAttributeMaxDynamicSharedMemorySize, dyn_smem);
        cudaStreamCreateWithFlags(&st[0], cudaStreamNonBlocking);
        cudaStreamCreateWithFlags(&st[1], cudaStreamNonBlocking);
        cudaEventCreateWithFlags(&evFork,    cudaEventDisableTiming);
        cudaEventCreateWithFlags(&evJoin[0], cudaEventDisableTiming);
        cudaEventCreateWithFlags(&evJoin[1], cudaEventDisableTiming);
        init_done = true;
    }

    // Shared prep on the (captured) default stream
    {
        dim3 blk(32, 8);
        transpose_kernel<<<dim3(QKV_N / 32, DMODEL / 32), blk>>>(Wqkv, wqkvT,
                                                                 DMODEL, QKV_N);
        transpose_kernel<<<dim3(DMODEL / 32, DMODEL / 32), blk>>>(Wout, woutT,
                                                                  DMODEL, DMODEL);
    }
    cudaEventRecord(evFork, 0);
    cudaStreamWaitEvent(st[0], evFork, 0);
    cudaStreamWaitEvent(st[1], evFork, 0);

    for (int c = 0; c < NCHUNK; c++) {
        cudaStream_t s = st[c & 1];
        const size_t ro = (size_t)c * CHROWS;
        const float* xc = x   + ro * DMODEL;
        __half* xtc     = xt  + ro * DMODEL;
        float* qkvc     = qkv + ro * QKV_N;
        __half* attc    = att + ro * DMODEL;
        float* outc     = out + ro * DMODEL;

        const int n16 = CHROWS * DMODEL / 16;
        conv_perm_kernel<<<(n16 + 255) / 256, 256, 0, s>>>(
            (const float4*)xc, xtc, n16);

        gemm_mma_f16<DMODEL><<<dim3(QKV_N / BN, CHROWS / BM),
                               GEMM_THREADS, dyn_smem, s>>>(
            xtc, wqkvT, qkvc, CHROWS, QKV_N);

        local_attn_kernel<<<CHROWS, 256, 0, s>>>(qkvc, bias, attc);

        gemm_mma_f16<DMODEL><<<dim3(DMODEL / BN, CHROWS / BM),
                               GEMM_THREADS, dyn_smem, s>>>(
            attc, woutT, outc, CHROWS, DMODEL);
    }

    cudaEventRecord(evJoin[0], st[0]);
    cudaEventRecord(evJoin[1], st[1]);
    cudaStreamWaitEvent(0, evJoin[0], 0);
    cudaStreamWaitEvent(0, evJoin[1], 0);
}